// round 10
// baseline (speedup 1.0000x reference)
#include <cuda_runtime.h>

#define Bz 256
#define Lz 8192
#define EPSf 1e-5f

// ---------------- scratch (no allocs allowed) ----------------
__device__ float g_Meff[Bz * 256];

// triangular index for c<=d
#define TRI(c, d) ((c)*16 - ((c) * ((c) + 1)) / 2 + (d))

// ---------------- gram + attn fused: one CTA per batch ----------------
__global__ void __launch_bounds__(256) gram_attn_kernel(
    const float* __restrict__ x, const float* __restrict__ wc1,
    const float* __restrict__ g1, const float* __restrict__ bt1,
    const float* __restrict__ m1, const float* __restrict__ v1,
    const float* __restrict__ wc2, const float* __restrict__ g2,
    const float* __restrict__ v2, const float* __restrict__ beta_cam) {
    int b = blockIdx.x;
    int tid = threadIdx.x;
    __shared__ float w1fs[64], b1fs[16];
    __shared__ float wsum[8][136];
    __shared__ float gram_s[256];
    __shared__ float As[256];
    if (tid < 64) {
        int d = tid >> 2;
        float s1 = g1[d] * rsqrtf(v1[d] + EPSf);
        w1fs[tid] = wc1[tid] * s1;
        if ((tid & 3) == 0) b1fs[d] = bt1[d] - m1[d] * s1;
    }
    __syncthreads();

    float acc[136];
#pragma unroll
    for (int t = 0; t < 136; t++) acc[t] = 0.f;

    const float* xb = x + (size_t)b * 4 * Lz;
    for (int it = 0; it < 32; it++) {
        int pos = it * 256 + tid;
        float xv0 = xb[0 * Lz + pos];
        float xv1 = xb[1 * Lz + pos];
        float xv2 = xb[2 * Lz + pos];
        float xv3 = xb[3 * Lz + pos];
        float c0[16];
#pragma unroll
        for (int d = 0; d < 16; d++) {
            float s = b1fs[d];
            s += xv0 * w1fs[d * 4 + 0];
            s += xv1 * w1fs[d * 4 + 1];
            s += xv2 * w1fs[d * 4 + 2];
            s += xv3 * w1fs[d * 4 + 3];
            c0[d] = fmaxf(s, 0.f);
        }
#pragma unroll
        for (int c = 0; c < 16; c++)
#pragma unroll
            for (int d = c; d < 16; d++)
                acc[TRI(c, d)] += c0[c] * c0[d];
    }

    int warp = tid >> 5, lane = tid & 31;
#pragma unroll
    for (int t = 0; t < 136; t++) {
        float v = acc[t];
        v += __shfl_xor_sync(0xffffffffu, v, 16);
        v += __shfl_xor_sync(0xffffffffu, v, 8);
        v += __shfl_xor_sync(0xffffffffu, v, 4);
        v += __shfl_xor_sync(0xffffffffu, v, 2);
        v += __shfl_xor_sync(0xffffffffu, v, 1);
        if (lane == 0) wsum[warp][t] = v;
    }
    __syncthreads();
    if (tid < 136) {
        float s = 0.f;
#pragma unroll
        for (int w = 0; w < 8; w++) s += wsum[w][tid];
        int c = 0, rem = tid;
        while (rem >= 16 - c) { rem -= 16 - c; c++; }
        int d = c + rem;
        gram_s[c * 16 + d] = s;
        if (d != c) gram_s[d * 16 + c] = s;
    }
    __syncthreads();

    // ---- attn: softmax(rowmax - gram) folded into Meff ----
    float g = gram_s[tid];
    float mn = g;
    mn = fminf(mn, __shfl_xor_sync(0xffffffffu, mn, 8, 16));
    mn = fminf(mn, __shfl_xor_sync(0xffffffffu, mn, 4, 16));
    mn = fminf(mn, __shfl_xor_sync(0xffffffffu, mn, 2, 16));
    mn = fminf(mn, __shfl_xor_sync(0xffffffffu, mn, 1, 16));
    float e = expf(mn - g);
    float s = e;
    s += __shfl_xor_sync(0xffffffffu, s, 8, 16);
    s += __shfl_xor_sync(0xffffffffu, s, 4, 16);
    s += __shfl_xor_sync(0xffffffffu, s, 2, 16);
    s += __shfl_xor_sync(0xffffffffu, s, 1, 16);
    float beta = beta_cam[0];
    As[tid] = beta * (e / s);
    __syncthreads();

    int c = tid >> 4, d = tid & 15;
    float s2c = g2[c] * rsqrtf(v2[c] + EPSf);
    float a = wc2[c * 16 + d];
#pragma unroll
    for (int e2 = 0; e2 < 16; e2++)
        a += wc2[c * 16 + e2] * As[e2 * 16 + d];
    g_Meff[b * 256 + tid] = s2c * a;
}

// ---------------- fused main kernel ----------------
#define TILE 512
#define XS_N 648          // x tile + halo, swizzled (raw 607 -> swz 644)
#define FE_STR 704        // fea0 per-channel stride (raw 557 -> SWZ4 693), 16B-mult
#define SWZ(i) ((i) + ((i) >> 4))
#define SWZ4(i) ((i) + (((i) >> 4) << 2))

#define OFF_XS 0
#define OFF_F0 (OFF_XS + 4 * XS_N)            // 2592
#define OFF_W00 (OFF_F0 + 8 * FE_STR)         // 8224
#define OFF_W01 (OFF_W00 + 1024)              // 9248
#define OFF_W02 (OFF_W01 + 1024)              // 10272
#define OFF_ME (OFF_W02 + 1024)               // 11296
#define OFF_W1F (OFF_ME + 256)                // 11552
#define OFF_B1F (OFF_W1F + 64)                // 11616
#define OFF_B2F (OFF_B1F + 16)                // 11632
#define OFF_B00 (OFF_B2F + 16)                // 11648
#define OFF_B01 (OFF_B00 + 8)                 // 11656
#define OFF_B02 (OFF_B01 + 8)                 // 11664
#define SMEM_FLOATS (OFF_B02 + 8)             // 11672 floats = 46688 B

__global__ void __launch_bounds__(256, 3) main_kernel(
    const float* __restrict__ x,
    const float* __restrict__ w00, const float* __restrict__ b00,
    const float* __restrict__ w01, const float* __restrict__ b01,
    const float* __restrict__ w02, const float* __restrict__ b02,
    const float* __restrict__ wc1, const float* __restrict__ g1,
    const float* __restrict__ bt1, const float* __restrict__ m1,
    const float* __restrict__ v1, const float* __restrict__ g2,
    const float* __restrict__ bt2, const float* __restrict__ m2,
    const float* __restrict__ v2,
    float* __restrict__ out) {
    extern __shared__ float sm[];
    int tile = blockIdx.x, b = blockIdx.y;
    int tid = threadIdx.x;
    int tstart = tile * TILE;

    float* xs = sm + OFF_XS;
    float* f0 = sm + OFF_F0;
    float* w00s = sm + OFF_W00;
    float* w01s = sm + OFF_W01;
    float* w02s = sm + OFF_W02;
    float* mef = sm + OFF_ME;
    float* w1fs = sm + OFF_W1F;
    float* b1fs = sm + OFF_B1F;
    float* b2fs = sm + OFF_B2F;
    float* b00s = sm + OFF_B00;
    float* b01s = sm + OFF_B01;
    float* b02s = sm + OFF_B02;

    // ---- load weights + fold BN locally + x tile (xs stored swizzled) ----
    for (int t = tid; t < 1024; t += 256) {
        w00s[t] = w00[t];
        w01s[t] = w01[t];
        w02s[t] = w02[t];
    }
    if (tid < 8) { b00s[tid] = b00[tid]; b01s[tid] = b01[tid]; b02s[tid] = b02[tid]; }
    if (tid < 64) {
        int d = tid >> 2;
        float s1 = g1[d] * rsqrtf(v1[d] + EPSf);
        w1fs[tid] = wc1[tid] * s1;
        if ((tid & 3) == 0) b1fs[d] = bt1[d] - m1[d] * s1;
    }
    if (tid < 16) {
        float s2 = g2[tid] * rsqrtf(v2[tid] + EPSf);
        b2fs[tid] = bt2[tid] - m2[tid] * s2;
    }
    mef[tid] = g_Meff[b * 256 + tid];

    const float* xb = x + (size_t)b * 4 * Lz;
    for (int t = tid; t < 4 * 608; t += 256) {
        int i = t / 608, p = t - i * 608;   // raw p in [0,608)
        int gq = tstart - 30 + p;           // xs[i][SWZ(p)] = x[i][tstart-30+p]
        xs[i * XS_N + SWZ(p)] = (gq >= 0 && gq < Lz) ? xb[i * Lz + gq] : 0.f;
    }
    __syncthreads();

    int o = tid >> 5, g = tid & 31;  // warp-uniform o -> weight broadcast
    float* outb = out + (size_t)b * 16 * Lz + tstart;

    // ---- Phase C: fea0[o][f], f in [0,558), 18 positions/lane, k-chunked ----
    {
        float acc[18];
#pragma unroll
        for (int p = 0; p < 18; p++) acc[p] = b00s[o];
#pragma unroll
        for (int i = 0; i < 4; i++) {
            const float* xr = xs + i * XS_N;
#pragma unroll
            for (int h = 0; h < 2; h++) {     // k-chunks [0,16), [16,32)
                float win[34];
#pragma unroll
                for (int t = 0; t < 34; t++)
                    win[t] = xr[SWZ(g * 18 + 16 * h + t)];
                const float4* wv = (const float4*)(w00s + o * 128 + i * 32 + 16 * h);
#pragma unroll
                for (int kq = 0; kq < 4; kq++) {
                    float4 wq = wv[kq];
#pragma unroll
                    for (int p = 0; p < 18; p++) acc[p] += win[p + 4 * kq + 0] * wq.x;
#pragma unroll
                    for (int p = 0; p < 18; p++) acc[p] += win[p + 4 * kq + 1] * wq.y;
#pragma unroll
                    for (int p = 0; p < 18; p++) acc[p] += win[p + 4 * kq + 2] * wq.z;
#pragma unroll
                    for (int p = 0; p < 18; p++) acc[p] += win[p + 4 * kq + 3] * wq.w;
                }
            }
        }
#pragma unroll
        for (int p = 0; p < 18; p++) {
            int f = g * 18 + p;
            if (f < 558) {
                int pg = tstart - 14 + f;
                f0[o * FE_STR + SWZ4(f)] = (pg >= 0 && pg <= Lz) ? acc[p] : 0.f;
            }
        }
    }
    __syncthreads();

    // ---- Phase D pass 1: fea1 channel o -> out[o] directly (gmem) ----
    {
        float a1[16];
#pragma unroll
        for (int p = 0; p < 16; p++) a1[p] = b01s[o];
#pragma unroll
        for (int j = 0; j < 8; j++) {
            // fea1 taps raw f0 idx 16g+7+p+k, p<16,k<16 -> raw [16g+7, 16g+38).
            // Load raw [16g+4, 16g+40) via quads 1-3, 5-8, 10 of the SWZ4 runs.
            const float4* f4 = (const float4*)(f0 + j * FE_STR + 20 * g);
            float winA[36];   // winA[t] = f0raw[16g+4+t]
            float4 q;
            q = f4[1];  winA[0] = q.x;  winA[1] = q.y;  winA[2] = q.z;  winA[3] = q.w;
            q = f4[2];  winA[4] = q.x;  winA[5] = q.y;  winA[6] = q.z;  winA[7] = q.w;
            q = f4[3];  winA[8] = q.x;  winA[9] = q.y;  winA[10] = q.z; winA[11] = q.w;
            q = f4[5];  winA[12] = q.x; winA[13] = q.y; winA[14] = q.z; winA[15] = q.w;
            q = f4[6];  winA[16] = q.x; winA[17] = q.y; winA[18] = q.z; winA[19] = q.w;
            q = f4[7];  winA[20] = q.x; winA[21] = q.y; winA[22] = q.z; winA[23] = q.w;
            q = f4[8];  winA[24] = q.x; winA[25] = q.y; winA[26] = q.z; winA[27] = q.w;
            q = f4[10]; winA[28] = q.x; winA[29] = q.y; winA[30] = q.z; winA[31] = q.w;
            q = f4[11]; winA[32] = q.x; winA[33] = q.y;
            const float4* w1v = (const float4*)(w01s + o * 128 + j * 16);
#pragma unroll
            for (int kq = 0; kq < 4; kq++) {
                float4 wq = w1v[kq];
                int k0 = 4 * kq;
                // tap raw 16g+7+p+k = winA[3+p+k]
#pragma unroll
                for (int p = 0; p < 16; p++) a1[p] += winA[3 + p + k0 + 0] * wq.x;
#pragma unroll
                for (int p = 0; p < 16; p++) a1[p] += winA[3 + p + k0 + 1] * wq.y;
#pragma unroll
                for (int p = 0; p < 16; p++) a1[p] += winA[3 + p + k0 + 2] * wq.z;
#pragma unroll
                for (int p = 0; p < 16; p++) a1[p] += winA[3 + p + k0 + 3] * wq.w;
            }
        }
        float* orow = outb + (size_t)o * Lz + g * 16;
#pragma unroll
        for (int p = 0; p < 16; p++) orow[p] = a1[p];
    }

    // ---- Phase D pass 2: fea2 channel o -> out[8+o] directly (gmem) ----
    {
        float a2[16];
#pragma unroll
        for (int p = 0; p < 16; p++) a2[p] = b02s[o];
#pragma unroll
        for (int j = 0; j < 8; j++) {
            // fea2 taps raw [16g, 16g+46): the full 12-quad window.
            const float4* f4 = (const float4*)(f0 + j * FE_STR + 20 * g);
            float win[46];
            float4 q;
            q = f4[0];  win[0] = q.x;  win[1] = q.y;  win[2] = q.z;  win[3] = q.w;
            q = f4[1];  win[4] = q.x;  win[5] = q.y;  win[6] = q.z;  win[7] = q.w;
            q = f4[2];  win[8] = q.x;  win[9] = q.y;  win[10] = q.z; win[11] = q.w;
            q = f4[3];  win[12] = q.x; win[13] = q.y; win[14] = q.z; win[15] = q.w;
            q = f4[5];  win[16] = q.x; win[17] = q.y; win[18] = q.z; win[19] = q.w;
            q = f4[6];  win[20] = q.x; win[21] = q.y; win[22] = q.z; win[23] = q.w;
            q = f4[7];  win[24] = q.x; win[25] = q.y; win[26] = q.z; win[27] = q.w;
            q = f4[8];  win[28] = q.x; win[29] = q.y; win[30] = q.z; win[31] = q.w;
            q = f4[10]; win[32] = q.x; win[33] = q.y; win[34] = q.z; win[35] = q.w;
            q = f4[11]; win[36] = q.x; win[37] = q.y; win[38] = q.z; win[39] = q.w;
            q = f4[12]; win[40] = q.x; win[41] = q.y; win[42] = q.z; win[43] = q.w;
            q = f4[13]; win[44] = q.x; win[45] = q.y;
            const float4* w2v = (const float4*)(w02s + o * 128 + j * 16);
#pragma unroll
            for (int kq = 0; kq < 4; kq++) {
                float4 wq = w2v[kq];
                int k0 = 4 * kq;
#pragma unroll
                for (int p = 0; p < 16; p++) a2[p] += win[p + 2 * k0 + 0] * wq.x;
#pragma unroll
                for (int p = 0; p < 16; p++) a2[p] += win[p + 2 * k0 + 2] * wq.y;
#pragma unroll
                for (int p = 0; p < 16; p++) a2[p] += win[p + 2 * k0 + 4] * wq.z;
#pragma unroll
                for (int p = 0; p < 16; p++) a2[p] += win[p + 2 * k0 + 6] * wq.w;
            }
        }
        float* orow = outb + (size_t)(8 + o) * Lz + g * 16;
#pragma unroll
        for (int p = 0; p < 16; p++) {
            int gl = tstart + g * 16 + p;
            // fea2 after pad(1,2): exactly 0 at l==0 and l>=8190
            orow[p] = (gl >= 1 && gl <= 8189) ? a2[p] : 0.f;
        }
    }
    __syncthreads();   // make D's gmem stores visible to F's loads (same CTA)

    // ---- Phase F: c0 -> c2 = relu(Meff@c0 + b2f), RMW-add onto out ----
#pragma unroll
    for (int it = 0; it < 2; it++) {
        int loc = tid + it * 256;
        float xv[4];
#pragma unroll
        for (int i = 0; i < 4; i++) xv[i] = xs[i * XS_N + SWZ(loc + 30)];
        float c0[16];
#pragma unroll
        for (int d = 0; d < 16; d++) {
            float s = b1fs[d];
#pragma unroll
            for (int i = 0; i < 4; i++) s += xv[i] * w1fs[d * 4 + i];
            c0[d] = fmaxf(s, 0.f);
        }
#pragma unroll
        for (int c = 0; c < 16; c++) {
            float cv = outb[(size_t)c * Lz + loc];
            const float4* mrow = (const float4*)(mef + c * 16);
            float4 m0 = mrow[0], m1 = mrow[1], m2 = mrow[2], m3 = mrow[3];
            float a = b2fs[c];
            a += m0.x * c0[0];  a += m0.y * c0[1];
            a += m0.z * c0[2];  a += m0.w * c0[3];
            a += m1.x * c0[4];  a += m1.y * c0[5];
            a += m1.z * c0[6];  a += m1.w * c0[7];
            a += m2.x * c0[8];  a += m2.y * c0[9];
            a += m2.z * c0[10]; a += m2.w * c0[11];
            a += m3.x * c0[12]; a += m3.y * c0[13];
            a += m3.z * c0[14]; a += m3.w * c0[15];
            a = fmaxf(a, 0.f);
            outb[(size_t)c * Lz + loc] = cv + a;
        }
    }
}

// ---------------- launch ----------------
extern "C" void kernel_launch(void* const* d_in, const int* in_sizes, int n_in,
                              void* d_out, int out_size) {
    const float* x    = (const float*)d_in[0];
    const float* w00  = (const float*)d_in[1];
    const float* b00  = (const float*)d_in[2];
    const float* w01  = (const float*)d_in[3];
    const float* b01  = (const float*)d_in[4];
    const float* w02  = (const float*)d_in[5];
    const float* b02  = (const float*)d_in[6];
    const float* wc1  = (const float*)d_in[7];
    const float* g1   = (const float*)d_in[8];
    const float* bt1  = (const float*)d_in[9];
    const float* m1   = (const float*)d_in[10];
    const float* v1   = (const float*)d_in[11];
    const float* beta = (const float*)d_in[12];
    const float* wc2  = (const float*)d_in[13];
    const float* g2   = (const float*)d_in[14];
    const float* bt2  = (const float*)d_in[15];
    const float* m2   = (const float*)d_in[16];
    const float* v2   = (const float*)d_in[17];
    float* out = (float*)d_out;

    cudaFuncSetAttribute(main_kernel, cudaFuncAttributeMaxDynamicSharedMemorySize,
                         SMEM_FLOATS * 4);

    gram_attn_kernel<<<Bz, 256>>>(x, wc1, g1, bt1, m1, v1, wc2, g2, v2, beta);
    main_kernel<<<dim3(Lz / TILE, Bz), 256, SMEM_FLOATS * 4>>>(
        x, w00, b00, w01, b01, w02, b02,
        wc1, g1, bt1, m1, v1, g2, bt2, m2, v2, out);
}

// round 11
// speedup vs baseline: 1.4276x; 1.4276x over previous
#include <cuda_runtime.h>

#define Bz 256
#define Lz 8192
#define EPSf 1e-5f

// ---------------- scratch (no allocs allowed) ----------------
__device__ float g_Meff[Bz * 256];

// triangular index for c<=d
#define TRI(c, d) ((c)*16 - ((c) * ((c) + 1)) / 2 + (d))

// ---------------- gram + attn fused: one CTA per batch ----------------
__global__ void __launch_bounds__(256) gram_attn_kernel(
    const float* __restrict__ x, const float* __restrict__ wc1,
    const float* __restrict__ g1, const float* __restrict__ bt1,
    const float* __restrict__ m1, const float* __restrict__ v1,
    const float* __restrict__ wc2, const float* __restrict__ g2,
    const float* __restrict__ v2, const float* __restrict__ beta_cam) {
    int b = blockIdx.x;
    int tid = threadIdx.x;
    __shared__ float w1fs[64], b1fs[16];
    __shared__ float wsum[8][136];
    __shared__ float gram_s[256];
    __shared__ float As[256];
    if (tid < 64) {
        int d = tid >> 2;
        float s1 = g1[d] * rsqrtf(v1[d] + EPSf);
        w1fs[tid] = wc1[tid] * s1;
        if ((tid & 3) == 0) b1fs[d] = bt1[d] - m1[d] * s1;
    }
    __syncthreads();

    float acc[136];
#pragma unroll
    for (int t = 0; t < 136; t++) acc[t] = 0.f;

    const float* xb = x + (size_t)b * 4 * Lz;
    for (int it = 0; it < 32; it++) {
        int pos = it * 256 + tid;
        float xv0 = xb[0 * Lz + pos];
        float xv1 = xb[1 * Lz + pos];
        float xv2 = xb[2 * Lz + pos];
        float xv3 = xb[3 * Lz + pos];
        float c0[16];
#pragma unroll
        for (int d = 0; d < 16; d++) {
            float s = b1fs[d];
            s += xv0 * w1fs[d * 4 + 0];
            s += xv1 * w1fs[d * 4 + 1];
            s += xv2 * w1fs[d * 4 + 2];
            s += xv3 * w1fs[d * 4 + 3];
            c0[d] = fmaxf(s, 0.f);
        }
#pragma unroll
        for (int c = 0; c < 16; c++)
#pragma unroll
            for (int d = c; d < 16; d++)
                acc[TRI(c, d)] += c0[c] * c0[d];
    }

    int warp = tid >> 5, lane = tid & 31;
#pragma unroll
    for (int t = 0; t < 136; t++) {
        float v = acc[t];
        v += __shfl_xor_sync(0xffffffffu, v, 16);
        v += __shfl_xor_sync(0xffffffffu, v, 8);
        v += __shfl_xor_sync(0xffffffffu, v, 4);
        v += __shfl_xor_sync(0xffffffffu, v, 2);
        v += __shfl_xor_sync(0xffffffffu, v, 1);
        if (lane == 0) wsum[warp][t] = v;
    }
    __syncthreads();
    if (tid < 136) {
        float s = 0.f;
#pragma unroll
        for (int w = 0; w < 8; w++) s += wsum[w][tid];
        int c = 0, rem = tid;
        while (rem >= 16 - c) { rem -= 16 - c; c++; }
        int d = c + rem;
        gram_s[c * 16 + d] = s;
        if (d != c) gram_s[d * 16 + c] = s;
    }
    __syncthreads();

    // ---- attn: softmax(rowmax - gram) folded into Meff ----
    float g = gram_s[tid];
    float mn = g;
    mn = fminf(mn, __shfl_xor_sync(0xffffffffu, mn, 8, 16));
    mn = fminf(mn, __shfl_xor_sync(0xffffffffu, mn, 4, 16));
    mn = fminf(mn, __shfl_xor_sync(0xffffffffu, mn, 2, 16));
    mn = fminf(mn, __shfl_xor_sync(0xffffffffu, mn, 1, 16));
    float e = expf(mn - g);
    float s = e;
    s += __shfl_xor_sync(0xffffffffu, s, 8, 16);
    s += __shfl_xor_sync(0xffffffffu, s, 4, 16);
    s += __shfl_xor_sync(0xffffffffu, s, 2, 16);
    s += __shfl_xor_sync(0xffffffffu, s, 1, 16);
    float beta = beta_cam[0];
    As[tid] = beta * (e / s);
    __syncthreads();

    int c = tid >> 4, d = tid & 15;
    float s2c = g2[c] * rsqrtf(v2[c] + EPSf);
    float a = wc2[c * 16 + d];
#pragma unroll
    for (int e2 = 0; e2 < 16; e2++)
        a += wc2[c * 16 + e2] * As[e2 * 16 + d];
    g_Meff[b * 256 + tid] = s2c * a;
}

// ---------------- fused main kernel ----------------
#define TILE 512
#define XS_N 648          // x tile + halo, swizzled (raw 607 -> swz 644)
#define FE_STR 704        // fea0 per-channel stride (raw 557 -> SWZ4 693), 16B-mult
#define ST_STR 544        // stage per-channel stride (raw 511 -> swz 542)
#define SWZ(i) ((i) + ((i) >> 4))
#define SWZ4(i) ((i) + (((i) >> 4) << 2))

#define OFF_XS 0
#define OFF_F0 (OFF_XS + 4 * XS_N)            // 2592
#define OFF_W00 (OFF_F0 + 8 * FE_STR)         // 8224
#define OFF_W01 (OFF_W00 + 1024)              // 9248
#define OFF_W02 (OFF_W01 + 1024)              // 10272
#define OFF_ME (OFF_W02 + 1024)               // 11296
#define OFF_W1F (OFF_ME + 256)                // 11552
#define OFF_B1F (OFF_W1F + 64)                // 11616
#define OFF_B2F (OFF_B1F + 16)                // 11632
#define OFF_B00 (OFF_B2F + 16)                // 11648
#define OFF_B01 (OFF_B00 + 8)                 // 11656
#define OFF_B02 (OFF_B01 + 8)                 // 11664
#define SMEM_FLOATS (OFF_B02 + 8)             // 11672 floats = 46688 B

// stg ALIASES [OFF_F0, OFF_ME): f0 + w00s + w01s + w02s = 5632+3*1024 = 8704
// floats = exactly 16*ST_STR. All four are dead once Phase D's accumulation
// finishes; a __syncthreads() separates the last f0/w read from the first
// stg write. stg max index 15*544+SWZ(511)=8702 < 8704.
#define OFF_STG OFF_F0

__global__ void __launch_bounds__(256, 3) main_kernel(
    const float* __restrict__ x,
    const float* __restrict__ w00, const float* __restrict__ b00,
    const float* __restrict__ w01, const float* __restrict__ b01,
    const float* __restrict__ w02, const float* __restrict__ b02,
    const float* __restrict__ wc1, const float* __restrict__ g1,
    const float* __restrict__ bt1, const float* __restrict__ m1,
    const float* __restrict__ v1, const float* __restrict__ g2,
    const float* __restrict__ bt2, const float* __restrict__ m2,
    const float* __restrict__ v2,
    float* __restrict__ out) {
    extern __shared__ float sm[];
    int tile = blockIdx.x, b = blockIdx.y;
    int tid = threadIdx.x;
    int tstart = tile * TILE;

    float* xs = sm + OFF_XS;
    float* f0 = sm + OFF_F0;
    float* w00s = sm + OFF_W00;
    float* w01s = sm + OFF_W01;
    float* w02s = sm + OFF_W02;
    float* mef = sm + OFF_ME;
    float* stg = sm + OFF_STG;   // aliases f0/w00s/w01s/w02s
    float* w1fs = sm + OFF_W1F;
    float* b1fs = sm + OFF_B1F;
    float* b2fs = sm + OFF_B2F;
    float* b00s = sm + OFF_B00;
    float* b01s = sm + OFF_B01;
    float* b02s = sm + OFF_B02;

    // ---- load weights + fold BN locally + x tile (xs stored swizzled) ----
    for (int t = tid; t < 1024; t += 256) {
        w00s[t] = w00[t];
        w01s[t] = w01[t];
        w02s[t] = w02[t];
    }
    if (tid < 8) { b00s[tid] = b00[tid]; b01s[tid] = b01[tid]; b02s[tid] = b02[tid]; }
    if (tid < 64) {
        int d = tid >> 2;
        float s1 = g1[d] * rsqrtf(v1[d] + EPSf);
        w1fs[tid] = wc1[tid] * s1;
        if ((tid & 3) == 0) b1fs[d] = bt1[d] - m1[d] * s1;
    }
    if (tid < 16) {
        float s2 = g2[tid] * rsqrtf(v2[tid] + EPSf);
        b2fs[tid] = bt2[tid] - m2[tid] * s2;
    }
    mef[tid] = g_Meff[b * 256 + tid];

    const float* xb = x + (size_t)b * 4 * Lz;
    for (int t = tid; t < 4 * 608; t += 256) {
        int i = t / 608, p = t - i * 608;   // raw p in [0,608)
        int gq = tstart - 30 + p;           // xs[i][SWZ(p)] = x[i][tstart-30+p]
        xs[i * XS_N + SWZ(p)] = (gq >= 0 && gq < Lz) ? xb[i * Lz + gq] : 0.f;
    }
    __syncthreads();

    int o = tid >> 5, g = tid & 31;  // warp-uniform o -> weight broadcast

    // ---- Phase C: fea0[o][f], f in [0,558), 18 positions/lane, k-chunked ----
    {
        float acc[18];
#pragma unroll
        for (int p = 0; p < 18; p++) acc[p] = b00s[o];
#pragma unroll
        for (int i = 0; i < 4; i++) {
            const float* xr = xs + i * XS_N;
#pragma unroll
            for (int h = 0; h < 2; h++) {     // k-chunks [0,16), [16,32)
                float win[34];
#pragma unroll
                for (int t = 0; t < 34; t++)
                    win[t] = xr[SWZ(g * 18 + 16 * h + t)];
                const float4* wv = (const float4*)(w00s + o * 128 + i * 32 + 16 * h);
#pragma unroll
                for (int kq = 0; kq < 4; kq++) {
                    float4 wq = wv[kq];
#pragma unroll
                    for (int p = 0; p < 18; p++) acc[p] += win[p + 4 * kq + 0] * wq.x;
#pragma unroll
                    for (int p = 0; p < 18; p++) acc[p] += win[p + 4 * kq + 1] * wq.y;
#pragma unroll
                    for (int p = 0; p < 18; p++) acc[p] += win[p + 4 * kq + 2] * wq.z;
#pragma unroll
                    for (int p = 0; p < 18; p++) acc[p] += win[p + 4 * kq + 3] * wq.w;
                }
            }
        }
#pragma unroll
        for (int p = 0; p < 18; p++) {
            int f = g * 18 + p;
            if (f < 558) {
                int pg = tstart - 14 + f;
                f0[o * FE_STR + SWZ4(f)] = (pg >= 0 && pg <= Lz) ? acc[p] : 0.f;
            }
        }
    }
    __syncthreads();

    // ---- Phase D pass 1: fea2 channel o (keep a2 in regs) ----
    float a2[16];
    {
#pragma unroll
        for (int p = 0; p < 16; p++) a2[p] = b02s[o];
#pragma unroll
        for (int j = 0; j < 8; j++) {
            // fea2 taps raw [16g, 16g+46): 12-quad window.
            const float4* f4 = (const float4*)(f0 + j * FE_STR + 20 * g);
            float win[46];
            float4 q;
            q = f4[0];  win[0] = q.x;  win[1] = q.y;  win[2] = q.z;  win[3] = q.w;
            q = f4[1];  win[4] = q.x;  win[5] = q.y;  win[6] = q.z;  win[7] = q.w;
            q = f4[2];  win[8] = q.x;  win[9] = q.y;  win[10] = q.z; win[11] = q.w;
            q = f4[3];  win[12] = q.x; win[13] = q.y; win[14] = q.z; win[15] = q.w;
            q = f4[5];  win[16] = q.x; win[17] = q.y; win[18] = q.z; win[19] = q.w;
            q = f4[6];  win[20] = q.x; win[21] = q.y; win[22] = q.z; win[23] = q.w;
            q = f4[7];  win[24] = q.x; win[25] = q.y; win[26] = q.z; win[27] = q.w;
            q = f4[8];  win[28] = q.x; win[29] = q.y; win[30] = q.z; win[31] = q.w;
            q = f4[10]; win[32] = q.x; win[33] = q.y; win[34] = q.z; win[35] = q.w;
            q = f4[11]; win[36] = q.x; win[37] = q.y; win[38] = q.z; win[39] = q.w;
            q = f4[12]; win[40] = q.x; win[41] = q.y; win[42] = q.z; win[43] = q.w;
            q = f4[13]; win[44] = q.x; win[45] = q.y;
            const float4* w2v = (const float4*)(w02s + o * 128 + j * 16);
#pragma unroll
            for (int kq = 0; kq < 4; kq++) {
                float4 wq = w2v[kq];
                int k0 = 4 * kq;
#pragma unroll
                for (int p = 0; p < 16; p++) a2[p] += win[p + 2 * k0 + 0] * wq.x;
#pragma unroll
                for (int p = 0; p < 16; p++) a2[p] += win[p + 2 * k0 + 2] * wq.y;
#pragma unroll
                for (int p = 0; p < 16; p++) a2[p] += win[p + 2 * k0 + 4] * wq.z;
#pragma unroll
                for (int p = 0; p < 16; p++) a2[p] += win[p + 2 * k0 + 6] * wq.w;
            }
        }
    }

    // ---- Phase D pass 2: fea1 channel o (keep a1 in regs) ----
    float a1[16];
    {
#pragma unroll
        for (int p = 0; p < 16; p++) a1[p] = b01s[o];
#pragma unroll
        for (int j = 0; j < 8; j++) {
            // fea1 taps raw [16g+7, 16g+38); load raw [16g+4, 16g+40): 9 quads.
            const float4* f4 = (const float4*)(f0 + j * FE_STR + 20 * g);
            float winA[36];   // winA[t] = f0raw[16g+4+t]
            float4 q;
            q = f4[1];  winA[0] = q.x;  winA[1] = q.y;  winA[2] = q.z;  winA[3] = q.w;
            q = f4[2];  winA[4] = q.x;  winA[5] = q.y;  winA[6] = q.z;  winA[7] = q.w;
            q = f4[3];  winA[8] = q.x;  winA[9] = q.y;  winA[10] = q.z; winA[11] = q.w;
            q = f4[5];  winA[12] = q.x; winA[13] = q.y; winA[14] = q.z; winA[15] = q.w;
            q = f4[6];  winA[16] = q.x; winA[17] = q.y; winA[18] = q.z; winA[19] = q.w;
            q = f4[7];  winA[20] = q.x; winA[21] = q.y; winA[22] = q.z; winA[23] = q.w;
            q = f4[8];  winA[24] = q.x; winA[25] = q.y; winA[26] = q.z; winA[27] = q.w;
            q = f4[10]; winA[28] = q.x; winA[29] = q.y; winA[30] = q.z; winA[31] = q.w;
            q = f4[11]; winA[32] = q.x; winA[33] = q.y;
            const float4* w1v = (const float4*)(w01s + o * 128 + j * 16);
#pragma unroll
            for (int kq = 0; kq < 4; kq++) {
                float4 wq = w1v[kq];
                int k0 = 4 * kq;
                // tap raw 16g+7+p+k = winA[3+p+k]
#pragma unroll
                for (int p = 0; p < 16; p++) a1[p] += winA[3 + p + k0 + 0] * wq.x;
#pragma unroll
                for (int p = 0; p < 16; p++) a1[p] += winA[3 + p + k0 + 1] * wq.y;
#pragma unroll
                for (int p = 0; p < 16; p++) a1[p] += winA[3 + p + k0 + 2] * wq.z;
#pragma unroll
                for (int p = 0; p < 16; p++) a1[p] += winA[3 + p + k0 + 3] * wq.w;
            }
        }
    }

    // All f0/w01s/w02s reads done chip^CTA-wide before stg overwrites them.
    __syncthreads();
#pragma unroll
    for (int p = 0; p < 16; p++) {
        int l = g * 16 + p;
        int gl = tstart + l;
        stg[o * ST_STR + SWZ(l)] = a1[p];
        // fea2 after pad(1,2): exactly 0 at l==0 and l>=8190
        stg[(8 + o) * ST_STR + SWZ(l)] = (gl >= 1 && gl <= 8189) ? a2[p] : 0.f;
    }
    __syncthreads();

    // ---- Phase F: c0 -> c2 = relu(Meff@c0 + b2f), add conv, store ----
#pragma unroll
    for (int it = 0; it < 2; it++) {
        int loc = tid + it * 256;
        int gl = tstart + loc;
        float xv[4];
#pragma unroll
        for (int i = 0; i < 4; i++) xv[i] = xs[i * XS_N + SWZ(loc + 30)];
        float c0[16];
#pragma unroll
        for (int d = 0; d < 16; d++) {
            float s = b1fs[d];
#pragma unroll
            for (int i = 0; i < 4; i++) s += xv[i] * w1fs[d * 4 + i];
            c0[d] = fmaxf(s, 0.f);
        }
#pragma unroll
        for (int c = 0; c < 16; c++) {
            const float4* mrow = (const float4*)(mef + c * 16);
            float4 m0 = mrow[0], m1 = mrow[1], m2 = mrow[2], m3 = mrow[3];
            float a = b2fs[c];
            a += m0.x * c0[0];  a += m0.y * c0[1];
            a += m0.z * c0[2];  a += m0.w * c0[3];
            a += m1.x * c0[4];  a += m1.y * c0[5];
            a += m1.z * c0[6];  a += m1.w * c0[7];
            a += m2.x * c0[8];  a += m2.y * c0[9];
            a += m2.z * c0[10]; a += m2.w * c0[11];
            a += m3.x * c0[12]; a += m3.y * c0[13];
            a += m3.z * c0[14]; a += m3.w * c0[15];
            a = fmaxf(a, 0.f);
            out[((size_t)b * 16 + c) * Lz + gl] = stg[c * ST_STR + SWZ(loc)] + a;
        }
    }
}

// ---------------- launch ----------------
extern "C" void kernel_launch(void* const* d_in, const int* in_sizes, int n_in,
                              void* d_out, int out_size) {
    const float* x    = (const float*)d_in[0];
    const float* w00  = (const float*)d_in[1];
    const float* b00  = (const float*)d_in[2];
    const float* w01  = (const float*)d_in[3];
    const float* b01  = (const float*)d_in[4];
    const float* w02  = (const float*)d_in[5];
    const float* b02  = (const float*)d_in[6];
    const float* wc1  = (const float*)d_in[7];
    const float* g1   = (const float*)d_in[8];
    const float* bt1  = (const float*)d_in[9];
    const float* m1   = (const float*)d_in[10];
    const float* v1   = (const float*)d_in[11];
    const float* beta = (const float*)d_in[12];
    const float* wc2  = (const float*)d_in[13];
    const float* g2   = (const float*)d_in[14];
    const float* bt2  = (const float*)d_in[15];
    const float* m2   = (const float*)d_in[16];
    const float* v2   = (const float*)d_in[17];
    float* out = (float*)d_out;

    cudaFuncSetAttribute(main_kernel, cudaFuncAttributeMaxDynamicSharedMemorySize,
                         SMEM_FLOATS * 4);

    gram_attn_kernel<<<Bz, 256>>>(x, wc1, g1, bt1, m1, v1, wc2, g2, v2, beta);
    main_kernel<<<dim3(Lz / TILE, Bz), 256, SMEM_FLOATS * 4>>>(
        x, w00, b00, w01, b01, w02, b02,
        wc1, g1, bt1, m1, v1, g2, bt2, m2, v2, out);
}

// round 12
// speedup vs baseline: 2.3033x; 1.6135x over previous
#include <cuda_runtime.h>

#define Bz 256
#define Lz 8192
#define EPSf 1e-5f

// ---------------- scratch (no allocs allowed) ----------------
__device__ float g_Meff[Bz * 256];

// triangular index for c<=d
#define TRI(c, d) ((c)*16 - ((c) * ((c) + 1)) / 2 + (d))

// ---------------- gram + attn fused: one CTA per batch ----------------
__global__ void __launch_bounds__(256) gram_attn_kernel(
    const float* __restrict__ x, const float* __restrict__ wc1,
    const float* __restrict__ g1, const float* __restrict__ bt1,
    const float* __restrict__ m1, const float* __restrict__ v1,
    const float* __restrict__ wc2, const float* __restrict__ g2,
    const float* __restrict__ v2, const float* __restrict__ beta_cam) {
    int b = blockIdx.x;
    int tid = threadIdx.x;
    __shared__ float w1fs[64], b1fs[16];
    __shared__ float wsum[8][136];
    __shared__ float gram_s[256];
    __shared__ float As[256];
    if (tid < 64) {
        int d = tid >> 2;
        float s1 = g1[d] * rsqrtf(v1[d] + EPSf);
        w1fs[tid] = wc1[tid] * s1;
        if ((tid & 3) == 0) b1fs[d] = bt1[d] - m1[d] * s1;
    }
    __syncthreads();

    float acc[136];
#pragma unroll
    for (int t = 0; t < 136; t++) acc[t] = 0.f;

    const float* xb = x + (size_t)b * 4 * Lz;
    for (int it = 0; it < 32; it++) {
        int pos = it * 256 + tid;
        float xv0 = xb[0 * Lz + pos];
        float xv1 = xb[1 * Lz + pos];
        float xv2 = xb[2 * Lz + pos];
        float xv3 = xb[3 * Lz + pos];
        float c0[16];
#pragma unroll
        for (int d = 0; d < 16; d++) {
            float s = b1fs[d];
            s += xv0 * w1fs[d * 4 + 0];
            s += xv1 * w1fs[d * 4 + 1];
            s += xv2 * w1fs[d * 4 + 2];
            s += xv3 * w1fs[d * 4 + 3];
            c0[d] = fmaxf(s, 0.f);
        }
#pragma unroll
        for (int c = 0; c < 16; c++)
#pragma unroll
            for (int d = c; d < 16; d++)
                acc[TRI(c, d)] += c0[c] * c0[d];
    }

    int warp = tid >> 5, lane = tid & 31;
#pragma unroll
    for (int t = 0; t < 136; t++) {
        float v = acc[t];
        v += __shfl_xor_sync(0xffffffffu, v, 16);
        v += __shfl_xor_sync(0xffffffffu, v, 8);
        v += __shfl_xor_sync(0xffffffffu, v, 4);
        v += __shfl_xor_sync(0xffffffffu, v, 2);
        v += __shfl_xor_sync(0xffffffffu, v, 1);
        if (lane == 0) wsum[warp][t] = v;
    }
    __syncthreads();
    if (tid < 136) {
        float s = 0.f;
#pragma unroll
        for (int w = 0; w < 8; w++) s += wsum[w][tid];
        int c = 0, rem = tid;
        while (rem >= 16 - c) { rem -= 16 - c; c++; }
        int d = c + rem;
        gram_s[c * 16 + d] = s;
        if (d != c) gram_s[d * 16 + c] = s;
    }
    __syncthreads();

    // ---- attn: softmax(rowmax - gram) folded into Meff ----
    float g = gram_s[tid];
    float mn = g;
    mn = fminf(mn, __shfl_xor_sync(0xffffffffu, mn, 8, 16));
    mn = fminf(mn, __shfl_xor_sync(0xffffffffu, mn, 4, 16));
    mn = fminf(mn, __shfl_xor_sync(0xffffffffu, mn, 2, 16));
    mn = fminf(mn, __shfl_xor_sync(0xffffffffu, mn, 1, 16));
    float e = expf(mn - g);
    float s = e;
    s += __shfl_xor_sync(0xffffffffu, s, 8, 16);
    s += __shfl_xor_sync(0xffffffffu, s, 4, 16);
    s += __shfl_xor_sync(0xffffffffu, s, 2, 16);
    s += __shfl_xor_sync(0xffffffffu, s, 1, 16);
    float beta = beta_cam[0];
    As[tid] = beta * (e / s);
    __syncthreads();

    int c = tid >> 4, d = tid & 15;
    float s2c = g2[c] * rsqrtf(v2[c] + EPSf);
    float a = wc2[c * 16 + d];
#pragma unroll
    for (int e2 = 0; e2 < 16; e2++)
        a += wc2[c * 16 + e2] * As[e2 * 16 + d];
    g_Meff[b * 256 + tid] = s2c * a;
}

// ---------------- fused main kernel ----------------
#define TILE 512
#define XS_N 648          // x tile + halo, swizzled (raw 607 -> swz 644)
#define FE_STR 704        // fea0 per-channel stride (raw 557 -> SWZ4 693), 16B-mult
#define ST_STR 544        // stage per-channel stride (raw 511 -> swz 542)
#define SWZ(i) ((i) + ((i) >> 4))
#define SWZ4(i) ((i) + (((i) >> 4) << 2))

#define OFF_XS 0
#define OFF_F0 (OFF_XS + 4 * XS_N)            // 2592
#define OFF_W00 (OFF_F0 + 8 * FE_STR)         // 8224
#define OFF_W01 (OFF_W00 + 1024)              // 9248
#define OFF_W02 (OFF_W01 + 1024)              // 10272
#define OFF_ME (OFF_W02 + 1024)               // 11296
#define OFF_W1F (OFF_ME + 256)                // 11552
#define OFF_B1F (OFF_W1F + 64)                // 11616
#define OFF_B2F (OFF_B1F + 16)                // 11632
#define OFF_B00 (OFF_B2F + 16)                // 11648
#define OFF_B01 (OFF_B00 + 8)                 // 11656
#define OFF_B02 (OFF_B01 + 8)                 // 11664
#define SMEM_FLOATS (OFF_B02 + 8)             // 11672 floats = 46688 B

// stg ALIASES [OFF_F0, OFF_ME): f0 + w00s + w01s + w02s = 5632+3*1024 = 8704
// floats = exactly 16*ST_STR. All four are dead once Phase D's accumulation
// finishes; a __syncthreads() separates the last f0/w read from the first
// stg write. stg max index 15*544+SWZ(511)=8702 < 8704.
#define OFF_STG OFF_F0

__global__ void __launch_bounds__(256, 3) main_kernel(
    const float* __restrict__ x,
    const float* __restrict__ w00, const float* __restrict__ b00,
    const float* __restrict__ w01, const float* __restrict__ b01,
    const float* __restrict__ w02, const float* __restrict__ b02,
    const float* __restrict__ wc1, const float* __restrict__ g1,
    const float* __restrict__ bt1, const float* __restrict__ m1,
    const float* __restrict__ v1, const float* __restrict__ g2,
    const float* __restrict__ bt2, const float* __restrict__ m2,
    const float* __restrict__ v2,
    float* __restrict__ out) {
    extern __shared__ float sm[];
    int tile = blockIdx.x, b = blockIdx.y;
    int tid = threadIdx.x;
    int tstart = tile * TILE;

    float* xs = sm + OFF_XS;
    float* f0 = sm + OFF_F0;
    float* w00s = sm + OFF_W00;
    float* w01s = sm + OFF_W01;
    float* w02s = sm + OFF_W02;
    float* mef = sm + OFF_ME;
    float* stg = sm + OFF_STG;   // aliases f0/w00s/w01s/w02s
    float* w1fs = sm + OFF_W1F;
    float* b1fs = sm + OFF_B1F;
    float* b2fs = sm + OFF_B2F;
    float* b00s = sm + OFF_B00;
    float* b01s = sm + OFF_B01;
    float* b02s = sm + OFF_B02;

    // ---- load weights + fold BN locally + x tile (xs stored swizzled) ----
    for (int t = tid; t < 1024; t += 256) {
        w00s[t] = w00[t];
        w01s[t] = w01[t];
        w02s[t] = w02[t];
    }
    if (tid < 8) { b00s[tid] = b00[tid]; b01s[tid] = b01[tid]; b02s[tid] = b02[tid]; }
    if (tid < 64) {
        int d = tid >> 2;
        float s1 = g1[d] * rsqrtf(v1[d] + EPSf);
        w1fs[tid] = wc1[tid] * s1;
        if ((tid & 3) == 0) b1fs[d] = bt1[d] - m1[d] * s1;
    }
    if (tid < 16) {
        float s2 = g2[tid] * rsqrtf(v2[tid] + EPSf);
        b2fs[tid] = bt2[tid] - m2[tid] * s2;
    }
    mef[tid] = g_Meff[b * 256 + tid];

    const float* xb = x + (size_t)b * 4 * Lz;
    for (int t = tid; t < 4 * 608; t += 256) {
        int i = t / 608, p = t - i * 608;   // raw p in [0,608)
        int gq = tstart - 30 + p;           // xs[i][SWZ(p)] = x[i][tstart-30+p]
        xs[i * XS_N + SWZ(p)] = (gq >= 0 && gq < Lz) ? xb[i * Lz + gq] : 0.f;
    }
    __syncthreads();

    int o = tid >> 5, g = tid & 31;  // warp-uniform o -> weight broadcast

    // ---- Phase C: fea0[o][f], f in [0,558), 18 positions/lane, k-chunked ----
    {
        float acc[18];
#pragma unroll
        for (int p = 0; p < 18; p++) acc[p] = b00s[o];
#pragma unroll
        for (int i = 0; i < 4; i++) {
            const float* xr = xs + i * XS_N;
#pragma unroll
            for (int h = 0; h < 2; h++) {     // k-chunks [0,16), [16,32)
                float win[34];
#pragma unroll
                for (int t = 0; t < 34; t++)
                    win[t] = xr[SWZ(g * 18 + 16 * h + t)];
                const float4* wv = (const float4*)(w00s + o * 128 + i * 32 + 16 * h);
#pragma unroll
                for (int kq = 0; kq < 4; kq++) {
                    float4 wq = wv[kq];
#pragma unroll
                    for (int p = 0; p < 18; p++) acc[p] += win[p + 4 * kq + 0] * wq.x;
#pragma unroll
                    for (int p = 0; p < 18; p++) acc[p] += win[p + 4 * kq + 1] * wq.y;
#pragma unroll
                    for (int p = 0; p < 18; p++) acc[p] += win[p + 4 * kq + 2] * wq.z;
#pragma unroll
                    for (int p = 0; p < 18; p++) acc[p] += win[p + 4 * kq + 3] * wq.w;
                }
            }
        }
#pragma unroll
        for (int p = 0; p < 18; p++) {
            int f = g * 18 + p;
            if (f < 558) {
                int pg = tstart - 14 + f;
                f0[o * FE_STR + SWZ4(f)] = (pg >= 0 && pg <= Lz) ? acc[p] : 0.f;
            }
        }
    }
    __syncthreads();

    // ---- Phase D: fea1 + fea2 channel o, k-SPLIT windows to cap registers ----
    // Per k-half the union of fea1/fea2 taps needs only 32/36 window floats,
    // so both accumulator sets (32 regs) + window fit under the 84-reg cap.
    // Accumulation order per output is j-major, k ascending == prior rounds.
    float a1[16], a2[16];
    {
#pragma unroll
        for (int p = 0; p < 16; p++) { a1[p] = b01s[o]; a2[p] = b02s[o]; }
#pragma unroll
        for (int j = 0; j < 8; j++) {
            const float4* f4 = (const float4*)(f0 + j * FE_STR + 20 * g);
            const float4* w1v = (const float4*)(w01s + o * 128 + j * 16);
            const float4* w2v = (const float4*)(w02s + o * 128 + j * 16);

            // -- k-half 0: k in [0,8); window = raw f0[16g .. 16g+32) --
            {
                float win[32];
                float4 q;
                q = f4[0]; win[0] = q.x;  win[1] = q.y;  win[2] = q.z;  win[3] = q.w;
                q = f4[1]; win[4] = q.x;  win[5] = q.y;  win[6] = q.z;  win[7] = q.w;
                q = f4[2]; win[8] = q.x;  win[9] = q.y;  win[10] = q.z; win[11] = q.w;
                q = f4[3]; win[12] = q.x; win[13] = q.y; win[14] = q.z; win[15] = q.w;
                q = f4[5]; win[16] = q.x; win[17] = q.y; win[18] = q.z; win[19] = q.w;
                q = f4[6]; win[20] = q.x; win[21] = q.y; win[22] = q.z; win[23] = q.w;
                q = f4[7]; win[24] = q.x; win[25] = q.y; win[26] = q.z; win[27] = q.w;
                q = f4[8]; win[28] = q.x; win[29] = q.y; win[30] = q.z; win[31] = q.w;
#pragma unroll
                for (int kq = 0; kq < 2; kq++) {
                    float4 wq = w2v[kq];
                    int k0 = 4 * kq;
                    // fea2 tap: raw p+2k -> win[p+2k], max p+14 = 29 < 32
#pragma unroll
                    for (int p = 0; p < 16; p++) a2[p] += win[p + 2 * k0 + 0] * wq.x;
#pragma unroll
                    for (int p = 0; p < 16; p++) a2[p] += win[p + 2 * k0 + 2] * wq.y;
#pragma unroll
                    for (int p = 0; p < 16; p++) a2[p] += win[p + 2 * k0 + 4] * wq.z;
#pragma unroll
                    for (int p = 0; p < 16; p++) a2[p] += win[p + 2 * k0 + 6] * wq.w;
                }
#pragma unroll
                for (int kq = 0; kq < 2; kq++) {
                    float4 wq = w1v[kq];
                    int k0 = 4 * kq;
                    // fea1 tap: raw p+k+7 -> win[p+k+7], max p+14 = 29 < 32
#pragma unroll
                    for (int p = 0; p < 16; p++) a1[p] += win[p + k0 + 7] * wq.x;
#pragma unroll
                    for (int p = 0; p < 16; p++) a1[p] += win[p + k0 + 8] * wq.y;
#pragma unroll
                    for (int p = 0; p < 16; p++) a1[p] += win[p + k0 + 9] * wq.z;
#pragma unroll
                    for (int p = 0; p < 16; p++) a1[p] += win[p + k0 + 10] * wq.w;
                }
            }

            // -- k-half 1: k in [8,16); window = raw f0[16g+12 .. 16g+48) --
            // win[t] = raw f0[16g + 12 + t], t < 36.
            {
                float win[36];
                float4 q;
                q = f4[3];  win[0] = q.x;  win[1] = q.y;  win[2] = q.z;  win[3] = q.w;
                q = f4[5];  win[4] = q.x;  win[5] = q.y;  win[6] = q.z;  win[7] = q.w;
                q = f4[6];  win[8] = q.x;  win[9] = q.y;  win[10] = q.z; win[11] = q.w;
                q = f4[7];  win[12] = q.x; win[13] = q.y; win[14] = q.z; win[15] = q.w;
                q = f4[8];  win[16] = q.x; win[17] = q.y; win[18] = q.z; win[19] = q.w;
                q = f4[10]; win[20] = q.x; win[21] = q.y; win[22] = q.z; win[23] = q.w;
                q = f4[11]; win[24] = q.x; win[25] = q.y; win[26] = q.z; win[27] = q.w;
                q = f4[12]; win[28] = q.x; win[29] = q.y; win[30] = q.z; win[31] = q.w;
                q = f4[13]; win[32] = q.x; win[33] = q.y; win[34] = q.z; win[35] = q.w;
#pragma unroll
                for (int kq = 2; kq < 4; kq++) {
                    float4 wq = w2v[kq];
                    int k0 = 4 * kq;
                    // fea2 tap: raw p+2k -> win[p+2k-12], max p+18 = 33 < 36
#pragma unroll
                    for (int p = 0; p < 16; p++) a2[p] += win[p + 2 * k0 - 12] * wq.x;
#pragma unroll
                    for (int p = 0; p < 16; p++) a2[p] += win[p + 2 * k0 - 10] * wq.y;
#pragma unroll
                    for (int p = 0; p < 16; p++) a2[p] += win[p + 2 * k0 - 8] * wq.z;
#pragma unroll
                    for (int p = 0; p < 16; p++) a2[p] += win[p + 2 * k0 - 6] * wq.w;
                }
#pragma unroll
                for (int kq = 2; kq < 4; kq++) {
                    float4 wq = w1v[kq];
                    int k0 = 4 * kq;
                    // fea1 tap: raw p+k+7 -> win[p+k-5], max p+10 = 25 < 36
#pragma unroll
                    for (int p = 0; p < 16; p++) a1[p] += win[p + k0 - 5] * wq.x;
#pragma unroll
                    for (int p = 0; p < 16; p++) a1[p] += win[p + k0 - 4] * wq.y;
#pragma unroll
                    for (int p = 0; p < 16; p++) a1[p] += win[p + k0 - 3] * wq.z;
#pragma unroll
                    for (int p = 0; p < 16; p++) a1[p] += win[p + k0 - 2] * wq.w;
                }
            }
        }
    }

    // All f0/w01s/w02s reads done CTA-wide before stg overwrites them.
    __syncthreads();
#pragma unroll
    for (int p = 0; p < 16; p++) {
        int l = g * 16 + p;
        int gl = tstart + l;
        stg[o * ST_STR + SWZ(l)] = a1[p];
        // fea2 after pad(1,2): exactly 0 at l==0 and l>=8190
        stg[(8 + o) * ST_STR + SWZ(l)] = (gl >= 1 && gl <= 8189) ? a2[p] : 0.f;
    }
    __syncthreads();

    // ---- Phase F: c0 -> c2 = relu(Meff@c0 + b2f), add conv, store ----
#pragma unroll
    for (int it = 0; it < 2; it++) {
        int loc = tid + it * 256;
        int gl = tstart + loc;
        float xv[4];
#pragma unroll
        for (int i = 0; i < 4; i++) xv[i] = xs[i * XS_N + SWZ(loc + 30)];
        float c0[16];
#pragma unroll
        for (int d = 0; d < 16; d++) {
            float s = b1fs[d];
#pragma unroll
            for (int i = 0; i < 4; i++) s += xv[i] * w1fs[d * 4 + i];
            c0[d] = fmaxf(s, 0.f);
        }
#pragma unroll
        for (int c = 0; c < 16; c++) {
            const float4* mrow = (const float4*)(mef + c * 16);
            float4 m0 = mrow[0], m1 = mrow[1], m2 = mrow[2], m3 = mrow[3];
            float a = b2fs[c];
            a += m0.x * c0[0];  a += m0.y * c0[1];
            a += m0.z * c0[2];  a += m0.w * c0[3];
            a += m1.x * c0[4];  a += m1.y * c0[5];
            a += m1.z * c0[6];  a += m1.w * c0[7];
            a += m2.x * c0[8];  a += m2.y * c0[9];
            a += m2.z * c0[10]; a += m2.w * c0[11];
            a += m3.x * c0[12]; a += m3.y * c0[13];
            a += m3.z * c0[14]; a += m3.w * c0[15];
            a = fmaxf(a, 0.f);
            out[((size_t)b * 16 + c) * Lz + gl] = stg[c * ST_STR + SWZ(loc)] + a;
        }
    }
}

// ---------------- launch ----------------
extern "C" void kernel_launch(void* const* d_in, const int* in_sizes, int n_in,
                              void* d_out, int out_size) {
    const float* x    = (const float*)d_in[0];
    const float* w00  = (const float*)d_in[1];
    const float* b00  = (const float*)d_in[2];
    const float* w01  = (const float*)d_in[3];
    const float* b01  = (const float*)d_in[4];
    const float* w02  = (const float*)d_in[5];
    const float* b02  = (const float*)d_in[6];
    const float* wc1  = (const float*)d_in[7];
    const float* g1   = (const float*)d_in[8];
    const float* bt1  = (const float*)d_in[9];
    const float* m1   = (const float*)d_in[10];
    const float* v1   = (const float*)d_in[11];
    const float* beta = (const float*)d_in[12];
    const float* wc2  = (const float*)d_in[13];
    const float* g2   = (const float*)d_in[14];
    const float* bt2  = (const float*)d_in[15];
    const float* m2   = (const float*)d_in[16];
    const float* v2   = (const float*)d_in[17];
    float* out = (float*)d_out;

    cudaFuncSetAttribute(main_kernel, cudaFuncAttributeMaxDynamicSharedMemorySize,
                         SMEM_FLOATS * 4);

    gram_attn_kernel<<<Bz, 256>>>(x, wc1, g1, bt1, m1, v1, wc2, g2, v2, beta);
    main_kernel<<<dim3(Lz / TILE, Bz), 256, SMEM_FLOATS * 4>>>(
        x, w00, b00, w01, b01, w02, b02,
        wc1, g1, bt1, m1, v1, g2, bt2, m2, v2, out);
}

// round 13
// speedup vs baseline: 2.7130x; 1.1779x over previous
#include <cuda_runtime.h>

#define Bz 256
#define Lz 8192
#define EPSf 1e-5f

// ---------------- scratch (no allocs allowed) ----------------
__device__ float g_Meff[Bz * 256];

// triangular index for c<=d
#define TRI(c, d) ((c)*16 - ((c) * ((c) + 1)) / 2 + (d))

// ---------------- gram + attn fused: one CTA per batch ----------------
__global__ void __launch_bounds__(256) gram_attn_kernel(
    const float* __restrict__ x, const float* __restrict__ wc1,
    const float* __restrict__ g1, const float* __restrict__ bt1,
    const float* __restrict__ m1, const float* __restrict__ v1,
    const float* __restrict__ wc2, const float* __restrict__ g2,
    const float* __restrict__ v2, const float* __restrict__ beta_cam) {
    int b = blockIdx.x;
    int tid = threadIdx.x;
    __shared__ float w1fs[64], b1fs[16];
    __shared__ float wsum[8][136];
    __shared__ float gram_s[256];
    __shared__ float As[256];
    if (tid < 64) {
        int d = tid >> 2;
        float s1 = g1[d] * rsqrtf(v1[d] + EPSf);
        w1fs[tid] = wc1[tid] * s1;
        if ((tid & 3) == 0) b1fs[d] = bt1[d] - m1[d] * s1;
    }
    __syncthreads();

    float acc[136];
#pragma unroll
    for (int t = 0; t < 136; t++) acc[t] = 0.f;

    const float* xb = x + (size_t)b * 4 * Lz;
    for (int it = 0; it < 32; it++) {
        int pos = it * 256 + tid;
        float xv0 = xb[0 * Lz + pos];
        float xv1 = xb[1 * Lz + pos];
        float xv2 = xb[2 * Lz + pos];
        float xv3 = xb[3 * Lz + pos];
        float c0[16];
#pragma unroll
        for (int d = 0; d < 16; d++) {
            float s = b1fs[d];
            s += xv0 * w1fs[d * 4 + 0];
            s += xv1 * w1fs[d * 4 + 1];
            s += xv2 * w1fs[d * 4 + 2];
            s += xv3 * w1fs[d * 4 + 3];
            c0[d] = fmaxf(s, 0.f);
        }
#pragma unroll
        for (int c = 0; c < 16; c++)
#pragma unroll
            for (int d = c; d < 16; d++)
                acc[TRI(c, d)] += c0[c] * c0[d];
    }

    int warp = tid >> 5, lane = tid & 31;
#pragma unroll
    for (int t = 0; t < 136; t++) {
        float v = acc[t];
        v += __shfl_xor_sync(0xffffffffu, v, 16);
        v += __shfl_xor_sync(0xffffffffu, v, 8);
        v += __shfl_xor_sync(0xffffffffu, v, 4);
        v += __shfl_xor_sync(0xffffffffu, v, 2);
        v += __shfl_xor_sync(0xffffffffu, v, 1);
        if (lane == 0) wsum[warp][t] = v;
    }
    __syncthreads();
    if (tid < 136) {
        float s = 0.f;
#pragma unroll
        for (int w = 0; w < 8; w++) s += wsum[w][tid];
        int c = 0, rem = tid;
        while (rem >= 16 - c) { rem -= 16 - c; c++; }
        int d = c + rem;
        gram_s[c * 16 + d] = s;
        if (d != c) gram_s[d * 16 + c] = s;
    }
    __syncthreads();

    // ---- attn: softmax(rowmax - gram) folded into Meff ----
    float g = gram_s[tid];
    float mn = g;
    mn = fminf(mn, __shfl_xor_sync(0xffffffffu, mn, 8, 16));
    mn = fminf(mn, __shfl_xor_sync(0xffffffffu, mn, 4, 16));
    mn = fminf(mn, __shfl_xor_sync(0xffffffffu, mn, 2, 16));
    mn = fminf(mn, __shfl_xor_sync(0xffffffffu, mn, 1, 16));
    float e = expf(mn - g);
    float s = e;
    s += __shfl_xor_sync(0xffffffffu, s, 8, 16);
    s += __shfl_xor_sync(0xffffffffu, s, 4, 16);
    s += __shfl_xor_sync(0xffffffffu, s, 2, 16);
    s += __shfl_xor_sync(0xffffffffu, s, 1, 16);
    float beta = beta_cam[0];
    As[tid] = beta * (e / s);
    __syncthreads();

    int c = tid >> 4, d = tid & 15;
    float s2c = g2[c] * rsqrtf(v2[c] + EPSf);
    float a = wc2[c * 16 + d];
#pragma unroll
    for (int e2 = 0; e2 < 16; e2++)
        a += wc2[c * 16 + e2] * As[e2 * 16 + d];
    g_Meff[b * 256 + tid] = s2c * a;
}

// ---------------- fused main kernel ----------------
#define TILE 512
#define XS_N 648          // x tile + halo, swizzled (raw 607 -> swz 644)
#define FE_STR 704        // fea0 per-channel stride (raw 557 -> SWZ4 693), 16B-mult
#define ST_STR 544        // stage per-channel stride (raw 511 -> swz 542)
#define SWZ(i) ((i) + ((i) >> 4))
#define SWZ4(i) ((i) + (((i) >> 4) << 2))

#define OFF_XS 0
#define OFF_F0 (OFF_XS + 4 * XS_N)            // 2592
#define OFF_W00 (OFF_F0 + 8 * FE_STR)         // 8224
#define OFF_W01 (OFF_W00 + 1024)              // 9248
#define OFF_W02 (OFF_W01 + 1024)              // 10272
#define OFF_ME (OFF_W02 + 1024)               // 11296
#define OFF_STG (OFF_ME + 256)                // 11552
#define OFF_W1F (OFF_STG + 16 * ST_STR)       // 20256
#define OFF_B1F (OFF_W1F + 64)                // 20320
#define OFF_B2F (OFF_B1F + 16)                // 20336
#define OFF_B00 (OFF_B2F + 16)                // 20352
#define OFF_B01 (OFF_B00 + 8)                 // 20360
#define OFF_B02 (OFF_B01 + 8)                 // 20368
#define SMEM_FLOATS (OFF_B02 + 8)             // 20376 floats = 81504 B

__global__ void __launch_bounds__(256, 2) main_kernel(
    const float* __restrict__ x,
    const float* __restrict__ w00, const float* __restrict__ b00,
    const float* __restrict__ w01, const float* __restrict__ b01,
    const float* __restrict__ w02, const float* __restrict__ b02,
    const float* __restrict__ wc1, const float* __restrict__ g1,
    const float* __restrict__ bt1, const float* __restrict__ m1,
    const float* __restrict__ v1, const float* __restrict__ g2,
    const float* __restrict__ bt2, const float* __restrict__ m2,
    const float* __restrict__ v2,
    float* __restrict__ out) {
    extern __shared__ float sm[];
    int tile = blockIdx.x, b = blockIdx.y;
    int tid = threadIdx.x;
    int tstart = tile * TILE;

    float* xs = sm + OFF_XS;
    float* f0 = sm + OFF_F0;
    float* w00s = sm + OFF_W00;
    float* w01s = sm + OFF_W01;
    float* w02s = sm + OFF_W02;
    float* mef = sm + OFF_ME;
    float* stg = sm + OFF_STG;
    float* w1fs = sm + OFF_W1F;
    float* b1fs = sm + OFF_B1F;
    float* b2fs = sm + OFF_B2F;
    float* b00s = sm + OFF_B00;
    float* b01s = sm + OFF_B01;
    float* b02s = sm + OFF_B02;

    // ---- load weights + fold BN locally + x tile (xs stored swizzled) ----
    for (int t = tid; t < 1024; t += 256) {
        w00s[t] = w00[t];
        w01s[t] = w01[t];
        w02s[t] = w02[t];
    }
    if (tid < 8) { b00s[tid] = b00[tid]; b01s[tid] = b01[tid]; b02s[tid] = b02[tid]; }
    if (tid < 64) {
        int d = tid >> 2;
        float s1 = g1[d] * rsqrtf(v1[d] + EPSf);
        w1fs[tid] = wc1[tid] * s1;
        if ((tid & 3) == 0) b1fs[d] = bt1[d] - m1[d] * s1;
    }
    if (tid < 16) {
        float s2 = g2[tid] * rsqrtf(v2[tid] + EPSf);
        b2fs[tid] = bt2[tid] - m2[tid] * s2;
    }
    mef[tid] = g_Meff[b * 256 + tid];

    const float* xb = x + (size_t)b * 4 * Lz;
    for (int t = tid; t < 4 * 608; t += 256) {
        int i = t / 608, p = t - i * 608;   // raw p in [0,608)
        int gq = tstart - 30 + p;           // xs[i][SWZ(p)] = x[i][tstart-30+p]
        xs[i * XS_N + SWZ(p)] = (gq >= 0 && gq < Lz) ? xb[i * Lz + gq] : 0.f;
    }
    __syncthreads();

    int o = tid >> 5, g = tid & 31;  // warp-uniform o -> weight broadcast

    // ---- Phase C: fea0[o][f], f in [0,558), 18 positions/lane ----
    {
        float acc[18];
#pragma unroll
        for (int p = 0; p < 18; p++) acc[p] = b00s[o];
#pragma unroll
        for (int i = 0; i < 4; i++) {
            const float* xr = xs + i * XS_N;
            float win[49];
#pragma unroll
            for (int t = 0; t < 49; t++) {
                int p = g * 18 + t;
                win[t] = xr[SWZ(p)];
            }
            const float4* wv = (const float4*)(w00s + o * 128 + i * 32);
#pragma unroll
            for (int kq = 0; kq < 8; kq++) {
                float4 wq = wv[kq];
#pragma unroll
                for (int p = 0; p < 18; p++) acc[p] += win[p + 4 * kq + 0] * wq.x;
#pragma unroll
                for (int p = 0; p < 18; p++) acc[p] += win[p + 4 * kq + 1] * wq.y;
#pragma unroll
                for (int p = 0; p < 18; p++) acc[p] += win[p + 4 * kq + 2] * wq.z;
#pragma unroll
                for (int p = 0; p < 18; p++) acc[p] += win[p + 4 * kq + 3] * wq.w;
            }
        }
#pragma unroll
        for (int p = 0; p < 18; p++) {
            int f = g * 18 + p;
            if (f < 558) {
                int pg = tstart - 14 + f;
                f0[o * FE_STR + SWZ4(f)] = (pg >= 0 && pg <= Lz) ? acc[p] : 0.f;
            }
        }
    }
    __syncthreads();

    // ---- Phase D: fea1 & fea2 via sliding window, float4 window+weight loads ----
    {
        float a1[16], a2[16];
#pragma unroll
        for (int p = 0; p < 16; p++) { a1[p] = b01s[o]; a2[p] = b02s[o]; }
#pragma unroll
        for (int j = 0; j < 8; j++) {
            // window covers raw f0 indices [16g, 16g+46); SWZ4 maps 16-blocks
            // to contiguous 16B-aligned runs at 20g, 20g+20, 20g+40.
            const float4* f4 = (const float4*)(f0 + j * FE_STR + 20 * g);
            float win[46];
            float4 q;
            q = f4[0];  win[0] = q.x;  win[1] = q.y;  win[2] = q.z;  win[3] = q.w;
            q = f4[1];  win[4] = q.x;  win[5] = q.y;  win[6] = q.z;  win[7] = q.w;
            q = f4[2];  win[8] = q.x;  win[9] = q.y;  win[10] = q.z; win[11] = q.w;
            q = f4[3];  win[12] = q.x; win[13] = q.y; win[14] = q.z; win[15] = q.w;
            q = f4[5];  win[16] = q.x; win[17] = q.y; win[18] = q.z; win[19] = q.w;
            q = f4[6];  win[20] = q.x; win[21] = q.y; win[22] = q.z; win[23] = q.w;
            q = f4[7];  win[24] = q.x; win[25] = q.y; win[26] = q.z; win[27] = q.w;
            q = f4[8];  win[28] = q.x; win[29] = q.y; win[30] = q.z; win[31] = q.w;
            q = f4[10]; win[32] = q.x; win[33] = q.y; win[34] = q.z; win[35] = q.w;
            q = f4[11]; win[36] = q.x; win[37] = q.y; win[38] = q.z; win[39] = q.w;
            q = f4[12]; win[40] = q.x; win[41] = q.y; win[42] = q.z; win[43] = q.w;
            q = f4[13]; win[44] = q.x; win[45] = q.y;
            const float4* w1v = (const float4*)(w01s + o * 128 + j * 16);
            const float4* w2v = (const float4*)(w02s + o * 128 + j * 16);
#pragma unroll
            for (int kq = 0; kq < 4; kq++) {
                float4 w1q = w1v[kq];
                float4 w2q = w2v[kq];
                int k0 = 4 * kq;
#pragma unroll
                for (int p = 0; p < 16; p++) {
                    a1[p] += win[p + k0 + 7] * w1q.x;
                    a2[p] += win[p + 2 * k0] * w2q.x;
                }
#pragma unroll
                for (int p = 0; p < 16; p++) {
                    a1[p] += win[p + k0 + 8] * w1q.y;
                    a2[p] += win[p + 2 * k0 + 2] * w2q.y;
                }
#pragma unroll
                for (int p = 0; p < 16; p++) {
                    a1[p] += win[p + k0 + 9] * w1q.z;
                    a2[p] += win[p + 2 * k0 + 4] * w2q.z;
                }
#pragma unroll
                for (int p = 0; p < 16; p++) {
                    a1[p] += win[p + k0 + 10] * w1q.w;
                    a2[p] += win[p + 2 * k0 + 6] * w2q.w;
                }
            }
        }
#pragma unroll
        for (int p = 0; p < 16; p++) {
            int l = g * 16 + p;
            int gl = tstart + l;
            stg[o * ST_STR + SWZ(l)] = a1[p];
            // fea2 after pad(1,2): exactly 0 at l==0 and l>=8190
            stg[(8 + o) * ST_STR + SWZ(l)] = (gl >= 1 && gl <= 8189) ? a2[p] : 0.f;
        }
    }
    __syncthreads();

    // ---- Phase F: both positions per Meff-row load ----
    {
        int loc0 = tid, loc1 = tid + 256;
        float c0a[16], c0b[16];
#pragma unroll
        for (int half = 0; half < 2; half++) {
            int loc = half ? loc1 : loc0;
            float xv[4];
#pragma unroll
            for (int i = 0; i < 4; i++) xv[i] = xs[i * XS_N + SWZ(loc + 30)];
#pragma unroll
            for (int d = 0; d < 16; d++) {
                float s = b1fs[d];
#pragma unroll
                for (int i = 0; i < 4; i++) s += xv[i] * w1fs[d * 4 + i];
                float r = fmaxf(s, 0.f);
                if (half) c0b[d] = r; else c0a[d] = r;
            }
        }
#pragma unroll
        for (int c = 0; c < 16; c++) {
            const float4* mrow = (const float4*)(mef + c * 16);
            float4 m0 = mrow[0], m1 = mrow[1], m2 = mrow[2], m3 = mrow[3];
            float bb = b2fs[c];
            float aa = bb, ab = bb;
            aa += m0.x * c0a[0];  ab += m0.x * c0b[0];
            aa += m0.y * c0a[1];  ab += m0.y * c0b[1];
            aa += m0.z * c0a[2];  ab += m0.z * c0b[2];
            aa += m0.w * c0a[3];  ab += m0.w * c0b[3];
            aa += m1.x * c0a[4];  ab += m1.x * c0b[4];
            aa += m1.y * c0a[5];  ab += m1.y * c0b[5];
            aa += m1.z * c0a[6];  ab += m1.z * c0b[6];
            aa += m1.w * c0a[7];  ab += m1.w * c0b[7];
            aa += m2.x * c0a[8];  ab += m2.x * c0b[8];
            aa += m2.y * c0a[9];  ab += m2.y * c0b[9];
            aa += m2.z * c0a[10]; ab += m2.z * c0b[10];
            aa += m2.w * c0a[11]; ab += m2.w * c0b[11];
            aa += m3.x * c0a[12]; ab += m3.x * c0b[12];
            aa += m3.y * c0a[13]; ab += m3.y * c0b[13];
            aa += m3.z * c0a[14]; ab += m3.z * c0b[14];
            aa += m3.w * c0a[15]; ab += m3.w * c0b[15];
            aa = fmaxf(aa, 0.f);
            ab = fmaxf(ab, 0.f);
            float* orow = out + ((size_t)b * 16 + c) * Lz + tstart;
            orow[loc0] = stg[c * ST_STR + SWZ(loc0)] + aa;
            orow[loc1] = stg[c * ST_STR + SWZ(loc1)] + ab;
        }
    }
}

// ---------------- launch ----------------
extern "C" void kernel_launch(void* const* d_in, const int* in_sizes, int n_in,
                              void* d_out, int out_size) {
    const float* x    = (const float*)d_in[0];
    const float* w00  = (const float*)d_in[1];
    const float* b00  = (const float*)d_in[2];
    const float* w01  = (const float*)d_in[3];
    const float* b01  = (const float*)d_in[4];
    const float* w02  = (const float*)d_in[5];
    const float* b02  = (const float*)d_in[6];
    const float* wc1  = (const float*)d_in[7];
    const float* g1   = (const float*)d_in[8];
    const float* bt1  = (const float*)d_in[9];
    const float* m1   = (const float*)d_in[10];
    const float* v1   = (const float*)d_in[11];
    const float* beta = (const float*)d_in[12];
    const float* wc2  = (const float*)d_in[13];
    const float* g2   = (const float*)d_in[14];
    const float* bt2  = (const float*)d_in[15];
    const float* m2   = (const float*)d_in[16];
    const float* v2   = (const float*)d_in[17];
    float* out = (float*)d_out;

    cudaFuncSetAttribute(main_kernel, cudaFuncAttributeMaxDynamicSharedMemorySize,
                         SMEM_FLOATS * 4);

    gram_attn_kernel<<<Bz, 256>>>(x, wc1, g1, bt1, m1, v1, wc2, g2, v2, beta);
    main_kernel<<<dim3(Lz / TILE, Bz), 256, SMEM_FLOATS * 4>>>(
        x, w00, b00, w01, b01, w02, b02,
        wc1, g1, bt1, m1, v1, g2, bt2, m2, v2, out);
}